// round 11
// baseline (speedup 1.0000x reference)
#include <cuda_runtime.h>
#include <cuda_bf16.h>
#include <cstdint>

// DiffAttention via mma.sync bf16 hi/lo-split.
// out[n,h,d] = sum_l sigmoid(q.k) * v / sum_l sigmoid(q.k);  N=L=4096, H=8, M=D=64.
// CTA = 128 query rows x 1 head; 8 warps x 16 rows; loop over L in 64-row tiles.
// S stays in registers. MMA issue order groups 8 independent accumulators
// between reuses of the same accumulator to cover HMMA latency at occ=2.

#define NN 4096
#define LL 4096
#define HH 8
#define MM 64
#define DD 64
#define BM 128
#define BL 64
#define NTHREADS 256
#define NITER (LL / BL)

// smem byte offsets, all rows 128B (64 bf16), SW128-swizzled
#define SQH 0            // Q hi 128x64 (16KB)
#define SQL 16384        // Q lo
#define SKH 32768        // K hi 64x64 [l][m] (8KB)
#define SKL 40960
#define SVH 49152        // V hi 64x64 [l][d] (8KB)
#define SVL 57344
#define SMEM_BYTES (65536 + 1024)

static __device__ __forceinline__ uint32_t smem_u32(const void* p) {
    uint32_t a;
    asm("{ .reg .u64 t; cvta.to.shared.u64 t, %1; cvt.u32.u64 %0, t; }" : "=r"(a) : "l"(p));
    return a;
}
static __device__ __forceinline__ uint32_t sw128(uint32_t off) {
    return off ^ ((off >> 3) & 0x70);
}
static __device__ __forceinline__ void ldmx4(uint32_t addr, uint32_t r[4]) {
    asm volatile("ldmatrix.sync.aligned.m8n8.x4.shared.b16 {%0,%1,%2,%3}, [%4];"
        : "=r"(r[0]), "=r"(r[1]), "=r"(r[2]), "=r"(r[3]) : "r"(addr));
}
static __device__ __forceinline__ void ldmx4t(uint32_t addr, uint32_t r[4]) {
    asm volatile("ldmatrix.sync.aligned.m8n8.x4.trans.shared.b16 {%0,%1,%2,%3}, [%4];"
        : "=r"(r[0]), "=r"(r[1]), "=r"(r[2]), "=r"(r[3]) : "r"(addr));
}
static __device__ __forceinline__ void mma16816(float d[4], const uint32_t a[4],
                                                uint32_t b0, uint32_t b1) {
    asm volatile(
        "mma.sync.aligned.m16n8k16.row.col.f32.bf16.bf16.f32 "
        "{%0,%1,%2,%3}, {%4,%5,%6,%7}, {%8,%9}, {%0,%1,%2,%3};"
        : "+f"(d[0]), "+f"(d[1]), "+f"(d[2]), "+f"(d[3])
        : "r"(a[0]), "r"(a[1]), "r"(a[2]), "r"(a[3]), "r"(b0), "r"(b1));
}

// split two floats into packed bf16x2 hi + bf16x2 lo (x ~= hi + lo)
static __device__ __forceinline__ void split2(float x0, float x1, uint32_t& hi, uint32_t& lo) {
    __nv_bfloat162 h2 = __floats2bfloat162_rn(x0, x1);
    float r0 = x0 - __bfloat162float(h2.x);
    float r1 = x1 - __bfloat162float(h2.y);
    __nv_bfloat162 l2 = __floats2bfloat162_rn(r0, r1);
    hi = *reinterpret_cast<uint32_t*>(&h2);
    lo = *reinterpret_cast<uint32_t*>(&l2);
}
static __device__ __forceinline__ float sigmoidf_fast(float x) {
    return __fdividef(1.0f, 1.0f + __expf(-x));
}

__global__ __launch_bounds__(NTHREADS, 2)
void diffattn_hmma(const float* __restrict__ Q, const float* __restrict__ K,
                   const float* __restrict__ V, float* __restrict__ out)
{
    extern __shared__ char smem_raw[];
    char* sp = (char*)((((uintptr_t)smem_raw) + 1023) & ~(uintptr_t)1023);
    const uint32_t sb = smem_u32(sp);

    const int tid = threadIdx.x;
    const int wid = tid >> 5;
    const int lid = tid & 31;
    const int h  = blockIdx.x & (HH - 1);
    const int n0 = (blockIdx.x >> 3) * BM;
    const int mw = wid * 16;               // this warp's query-row block
    const int t4 = lid >> 3, r8 = lid & 7; // ldmatrix lane decomposition

    // ---- stage Q tile once: split to bf16 hi/lo, SW128-swizzled [row][m] ----
    #pragma unroll
    for (int i = 0; i < 8; i++) {
        const int c = tid + i * NTHREADS;
        const int row = c >> 4, m4 = c & 15;
        const float4 t = *(const float4*)(Q + ((size_t)(n0 + row) * HH + h) * MM + m4 * 4);
        uint32_t h0, l0r, h1, l1r;
        split2(t.x, t.y, h0, l0r); split2(t.z, t.w, h1, l1r);
        const uint32_t off = sw128(row * 128 + m4 * 8);
        *(uint2*)(sp + SQH + off) = make_uint2(h0, h1);
        *(uint2*)(sp + SQL + off) = make_uint2(l0r, l1r);
    }
    __syncthreads();

    float oacc[8][4];
    #pragma unroll
    for (int j = 0; j < 8; j++)
        #pragma unroll
        for (int i = 0; i < 4; i++) oacc[j][i] = 0.f;
    float normLo = 0.f, normHi = 0.f;

    const int a_row = mw + (t4 & 1) * 8 + r8;     // GEMM1 A-frag row
    const int b_row = (t4 >> 1) * 8 + r8;          // GEMM1 B-frag base row (+p*16)
    const int v_row = (t4 & 1) * 8 + r8;           // GEMM2 B-frag base row (+kk*16)

    for (int lt = 0; lt < NITER; lt++) {
        const int l0g = lt * BL;

        // ---- stage K tile [l][m] and V tile [l][d], bf16 hi/lo ----
        // 64x64 floats = 1024 float4 = 4 rounds of 256 threads
        #pragma unroll
        for (int i = 0; i < 4; i++) {
            const int c = tid + i * NTHREADS;
            const int row = c >> 4, m4 = c & 15;
            const float4 t = *(const float4*)(K + ((size_t)(l0g + row) * HH + h) * MM + m4 * 4);
            uint32_t h0, l0r, h1, l1r;
            split2(t.x, t.y, h0, l0r); split2(t.z, t.w, h1, l1r);
            const uint32_t off = sw128(row * 128 + m4 * 8);
            *(uint2*)(sp + SKH + off) = make_uint2(h0, h1);
            *(uint2*)(sp + SKL + off) = make_uint2(l0r, l1r);
        }
        #pragma unroll
        for (int i = 0; i < 4; i++) {
            const int c = tid + i * NTHREADS;
            const int row = c >> 4, d4 = c & 15;
            const float4 t = *(const float4*)(V + ((size_t)(l0g + row) * HH + h) * DD + d4 * 4);
            uint32_t h0, l0r, h1, l1r;
            split2(t.x, t.y, h0, l0r); split2(t.z, t.w, h1, l1r);
            const uint32_t off = sw128(row * 128 + d4 * 8);
            *(uint2*)(sp + SVH + off) = make_uint2(h0, h1);
            *(uint2*)(sp + SVL + off) = make_uint2(l0r, l1r);
        }
        __syncthreads();

        // ---- GEMM1: S[16x64] = Q K^T (qh*kh + qh*kl + ql*kh) ----
        // per k-step: load all 8 B-frags, then 3 term-groups of 8 independent MMAs
        float sacc[8][4];
        #pragma unroll
        for (int j = 0; j < 8; j++)
            #pragma unroll
            for (int i = 0; i < 4; i++) sacc[j][i] = 0.f;

        #pragma unroll
        for (int k = 0; k < 4; k++) {
            uint32_t aqh[4], aql[4];
            const uint32_t aoff = sw128(a_row * 128 + (k * 16 + (t4 >> 1) * 8) * 2);
            ldmx4(sb + SQH + aoff, aqh);
            ldmx4(sb + SQL + aoff, aql);
            uint32_t bh[4][4], bl[4][4];
            #pragma unroll
            for (int p = 0; p < 4; p++) {
                const uint32_t boff = sw128((p * 16 + b_row) * 128 + (k * 16 + (t4 & 1) * 8) * 2);
                ldmx4(sb + SKH + boff, bh[p]);
                ldmx4(sb + SKL + boff, bl[p]);
            }
            #pragma unroll
            for (int p = 0; p < 4; p++) {
                mma16816(sacc[2*p],   aqh, bh[p][0], bh[p][1]);
                mma16816(sacc[2*p+1], aqh, bh[p][2], bh[p][3]);
            }
            #pragma unroll
            for (int p = 0; p < 4; p++) {
                mma16816(sacc[2*p],   aqh, bl[p][0], bl[p][1]);
                mma16816(sacc[2*p+1], aqh, bl[p][2], bl[p][3]);
            }
            #pragma unroll
            for (int p = 0; p < 4; p++) {
                mma16816(sacc[2*p],   aql, bh[p][0], bh[p][1]);
                mma16816(sacc[2*p+1], aql, bh[p][2], bh[p][3]);
            }
        }

        // ---- GEMM2: O[16x64] += S V (sh*vh + sh*vl + sl*vh), kk outer ----
        // sigmoid+split done per kk (8 sacc values) to interleave MUFU with tensor
        #pragma unroll
        for (int kk = 0; kk < 4; kk++) {
            uint32_t vh[4][4], vl[4][4];
            #pragma unroll
            for (int p = 0; p < 4; p++) {
                const uint32_t boff = sw128((kk * 16 + v_row) * 128 + (p * 16 + (t4 >> 1) * 8) * 2);
                ldmx4t(sb + SVH + boff, vh[p]);
                ldmx4t(sb + SVL + boff, vl[p]);
            }
            // sigmoid + norm + hi/lo split of this kk's S slice (A-frag for GEMM2)
            uint32_t sh[4], sl[4];
            {
                float s0[4], s1[4];
                #pragma unroll
                for (int i = 0; i < 4; i++) {
                    s0[i] = sigmoidf_fast(sacc[2*kk][i]);
                    s1[i] = sigmoidf_fast(sacc[2*kk+1][i]);
                }
                normLo += (s0[0] + s0[1]) + (s1[0] + s1[1]);
                normHi += (s0[2] + s0[3]) + (s1[2] + s1[3]);
                split2(s0[0], s0[1], sh[0], sl[0]);
                split2(s0[2], s0[3], sh[1], sl[1]);
                split2(s1[0], s1[1], sh[2], sl[2]);
                split2(s1[2], s1[3], sh[3], sl[3]);
            }
            #pragma unroll
            for (int p = 0; p < 4; p++) {
                mma16816(oacc[2*p],   sh, vh[p][0], vh[p][1]);
                mma16816(oacc[2*p+1], sh, vh[p][2], vh[p][3]);
            }
            #pragma unroll
            for (int p = 0; p < 4; p++) {
                mma16816(oacc[2*p],   sh, vl[p][0], vl[p][1]);
                mma16816(oacc[2*p+1], sh, vl[p][2], vl[p][3]);
            }
            #pragma unroll
            for (int p = 0; p < 4; p++) {
                mma16816(oacc[2*p],   sl, vh[p][0], vh[p][1]);
                mma16816(oacc[2*p+1], sl, vh[p][2], vh[p][3]);
            }
        }
        __syncthreads();   // protect K/V tiles before next iteration overwrites
    }

    // ---- finalize: quad-reduce norm (lanes lid&~3 share a row), scale, store ----
    #pragma unroll
    for (int m = 1; m <= 2; m <<= 1) {
        normLo += __shfl_xor_sync(0xffffffffu, normLo, m);
        normHi += __shfl_xor_sync(0xffffffffu, normHi, m);
    }
    const float invLo = 1.0f / normLo;
    const float invHi = 1.0f / normHi;

    const int rowLo = n0 + mw + (lid >> 2);
    const int rowHi = rowLo + 8;
    const int cbase = (lid & 3) * 2;
    #pragma unroll
    for (int j = 0; j < 8; j++) {
        float2 lo = make_float2(oacc[j][0] * invLo, oacc[j][1] * invLo);
        float2 hi = make_float2(oacc[j][2] * invHi, oacc[j][3] * invHi);
        *(float2*)(out + ((size_t)rowLo * HH + h) * DD + j * 8 + cbase) = lo;
        *(float2*)(out + ((size_t)rowHi * HH + h) * DD + j * 8 + cbase) = hi;
    }
}

extern "C" void kernel_launch(void* const* d_in, const int* in_sizes, int n_in,
                              void* d_out, int out_size)
{
    const float* queries = (const float*)d_in[0];
    const float* keys    = (const float*)d_in[1];
    const float* values  = (const float*)d_in[2];
    float* out = (float*)d_out;

    cudaFuncSetAttribute(diffattn_hmma,
                         cudaFuncAttributeMaxDynamicSharedMemorySize, SMEM_BYTES);

    const dim3 grid((NN / BM) * HH);   // 32 * 8 = 256 CTAs
    diffattn_hmma<<<grid, NTHREADS, SMEM_BYTES>>>(queries, keys, values, out);
}

// round 12
// speedup vs baseline: 1.6108x; 1.6108x over previous
#include <cuda_runtime.h>
#include <cuda_bf16.h>
#include <cstdint>

// DiffAttention via mma.sync bf16 hi/lo-split (R4 structure restored).
// out[n,h,d] = sum_l sigmoid(q.k) * v / sum_l sigmoid(q.k);  N=L=4096, H=8, M=D=64.
// CTA = 128 query rows x 1 head; 8 warps x 16 rows; loop over L in 64-row tiles.
// S stays in registers between GEMM1 and GEMM2. Q A-frags persistent in regs.
// MMA pattern: load one (p,k) B-frag pair, consume immediately (small operand
// register footprint -> no RF bank-conflict slowdown; see R11 post-mortem).
// Deltas vs R4: sigmoid = 1x MUFU.TANH; K/V staging LDGs all issued before splits.

#define NN 4096
#define LL 4096
#define HH 8
#define MM 64
#define DD 64
#define BM 128
#define BL 64
#define NTHREADS 256
#define NITER (LL / BL)

// smem byte offsets, all rows 128B (64 bf16), SW128-swizzled
#define SQH 0            // Q hi 128x64 (16KB)
#define SQL 16384        // Q lo
#define SKH 32768        // K hi 64x64 [l][m] (8KB)
#define SKL 40960
#define SVH 49152        // V hi 64x64 [l][d] (8KB)
#define SVL 57344
#define SMEM_BYTES (65536 + 1024)

static __device__ __forceinline__ uint32_t smem_u32(const void* p) {
    uint32_t a;
    asm("{ .reg .u64 t; cvta.to.shared.u64 t, %1; cvt.u32.u64 %0, t; }" : "=r"(a) : "l"(p));
    return a;
}
static __device__ __forceinline__ uint32_t sw128(uint32_t off) {
    return off ^ ((off >> 3) & 0x70);
}
static __device__ __forceinline__ void ldmx4(uint32_t addr, uint32_t r[4]) {
    asm volatile("ldmatrix.sync.aligned.m8n8.x4.shared.b16 {%0,%1,%2,%3}, [%4];"
        : "=r"(r[0]), "=r"(r[1]), "=r"(r[2]), "=r"(r[3]) : "r"(addr));
}
static __device__ __forceinline__ void ldmx4t(uint32_t addr, uint32_t r[4]) {
    asm volatile("ldmatrix.sync.aligned.m8n8.x4.trans.shared.b16 {%0,%1,%2,%3}, [%4];"
        : "=r"(r[0]), "=r"(r[1]), "=r"(r[2]), "=r"(r[3]) : "r"(addr));
}
static __device__ __forceinline__ void mma16816(float d[4], const uint32_t a[4],
                                                uint32_t b0, uint32_t b1) {
    asm volatile(
        "mma.sync.aligned.m16n8k16.row.col.f32.bf16.bf16.f32 "
        "{%0,%1,%2,%3}, {%4,%5,%6,%7}, {%8,%9}, {%0,%1,%2,%3};"
        : "+f"(d[0]), "+f"(d[1]), "+f"(d[2]), "+f"(d[3])
        : "r"(a[0]), "r"(a[1]), "r"(a[2]), "r"(a[3]), "r"(b0), "r"(b1));
}

// split two floats into packed bf16x2 hi + bf16x2 lo (x ~= hi + lo)
static __device__ __forceinline__ void split2(float x0, float x1, uint32_t& hi, uint32_t& lo) {
    __nv_bfloat162 h2 = __floats2bfloat162_rn(x0, x1);
    float r0 = x0 - __bfloat162float(h2.x);
    float r1 = x1 - __bfloat162float(h2.y);
    __nv_bfloat162 l2 = __floats2bfloat162_rn(r0, r1);
    hi = *reinterpret_cast<uint32_t*>(&h2);
    lo = *reinterpret_cast<uint32_t*>(&l2);
}
// sigmoid(x) = 0.5*tanh(x/2) + 0.5 — single MUFU.TANH (tanh.approx: sm_75+ baseline PTX)
static __device__ __forceinline__ float sigmoidf_fast(float x) {
    float t;
    asm("tanh.approx.f32 %0, %1;" : "=f"(t) : "f"(x * 0.5f));
    return fmaf(t, 0.5f, 0.5f);
}

__global__ __launch_bounds__(NTHREADS, 2)
void diffattn_hmma(const float* __restrict__ Q, const float* __restrict__ K,
                   const float* __restrict__ V, float* __restrict__ out)
{
    extern __shared__ char smem_raw[];
    char* sp = (char*)((((uintptr_t)smem_raw) + 1023) & ~(uintptr_t)1023);
    const uint32_t sb = smem_u32(sp);

    const int tid = threadIdx.x;
    const int wid = tid >> 5;
    const int lid = tid & 31;
    const int h  = blockIdx.x & (HH - 1);
    const int n0 = (blockIdx.x >> 3) * BM;
    const int mw = wid * 16;               // this warp's query-row block
    const int t4 = lid >> 3, r8 = lid & 7; // ldmatrix lane decomposition

    // ---- stage Q tile once: split to bf16 hi/lo, SW128-swizzled [row][m] ----
    #pragma unroll
    for (int i = 0; i < 8; i++) {
        const int c = tid + i * NTHREADS;
        const int row = c >> 4, m4 = c & 15;
        const float4 t = *(const float4*)(Q + ((size_t)(n0 + row) * HH + h) * MM + m4 * 4);
        uint32_t h0, l0r, h1, l1r;
        split2(t.x, t.y, h0, l0r); split2(t.z, t.w, h1, l1r);
        const uint32_t off = sw128(row * 128 + m4 * 8);
        *(uint2*)(sp + SQH + off) = make_uint2(h0, h1);
        *(uint2*)(sp + SQL + off) = make_uint2(l0r, l1r);
    }
    __syncthreads();

    // ---- preload Q A-fragments (persistent): 4 k-steps x (hi,lo) ----
    uint32_t qh[4][4], ql[4][4];
    {
        #pragma unroll
        for (int k = 0; k < 4; k++) {
            const int row = mw + (t4 & 1) * 8 + r8;
            const int kc  = k * 16 + (t4 >> 1) * 8;
            const uint32_t off = sw128(row * 128 + kc * 2);
            ldmx4(sb + SQH + off, qh[k]);
            ldmx4(sb + SQL + off, ql[k]);
        }
    }

    float oacc[8][4];
    #pragma unroll
    for (int j = 0; j < 8; j++)
        #pragma unroll
        for (int i = 0; i < 4; i++) oacc[j][i] = 0.f;
    float normLo = 0.f, normHi = 0.f;

    for (int lt = 0; lt < NITER; lt++) {
        const int l0g = lt * BL;

        // ---- stage K tile [l][m] and V tile [l][d], bf16 hi/lo ----
        // issue all 8 LDG.128 first (MLP=8), then split+store
        {
            float4 kt[4], vt[4];
            #pragma unroll
            for (int i = 0; i < 4; i++) {
                const int c = tid + i * NTHREADS;
                const int row = c >> 4, m4 = c & 15;
                kt[i] = *(const float4*)(K + ((size_t)(l0g + row) * HH + h) * MM + m4 * 4);
            }
            #pragma unroll
            for (int i = 0; i < 4; i++) {
                const int c = tid + i * NTHREADS;
                const int row = c >> 4, d4 = c & 15;
                vt[i] = *(const float4*)(V + ((size_t)(l0g + row) * HH + h) * DD + d4 * 4);
            }
            #pragma unroll
            for (int i = 0; i < 4; i++) {
                const int c = tid + i * NTHREADS;
                const int row = c >> 4, m4 = c & 15;
                uint32_t h0, l0r, h1, l1r;
                split2(kt[i].x, kt[i].y, h0, l0r); split2(kt[i].z, kt[i].w, h1, l1r);
                const uint32_t off = sw128(row * 128 + m4 * 8);
                *(uint2*)(sp + SKH + off) = make_uint2(h0, h1);
                *(uint2*)(sp + SKL + off) = make_uint2(l0r, l1r);
            }
            #pragma unroll
            for (int i = 0; i < 4; i++) {
                const int c = tid + i * NTHREADS;
                const int row = c >> 4, d4 = c & 15;
                uint32_t h0, l0r, h1, l1r;
                split2(vt[i].x, vt[i].y, h0, l0r); split2(vt[i].z, vt[i].w, h1, l1r);
                const uint32_t off = sw128(row * 128 + d4 * 8);
                *(uint2*)(sp + SVH + off) = make_uint2(h0, h1);
                *(uint2*)(sp + SVL + off) = make_uint2(l0r, l1r);
            }
        }
        __syncthreads();

        // ---- GEMM1: S[16x64] = Q K^T (qh*kh + qh*kl + ql*kh) ----
        float sacc[8][4];
        #pragma unroll
        for (int j = 0; j < 8; j++)
            #pragma unroll
            for (int i = 0; i < 4; i++) sacc[j][i] = 0.f;

        #pragma unroll
        for (int p = 0; p < 4; p++) {          // n (l-col) pair: tiles 2p, 2p+1
            #pragma unroll
            for (int k = 0; k < 4; k++) {      // k (m) step
                const int nrow = p * 16 + (t4 >> 1) * 8 + r8;
                const int kc   = k * 16 + (t4 & 1) * 8;
                const uint32_t off = sw128(nrow * 128 + kc * 2);
                uint32_t bh[4], bl[4];
                ldmx4(sb + SKH + off, bh);
                ldmx4(sb + SKL + off, bl);
                mma16816(sacc[2*p],   qh[k], bh[0], bh[1]);
                mma16816(sacc[2*p+1], qh[k], bh[2], bh[3]);
                mma16816(sacc[2*p],   qh[k], bl[0], bl[1]);
                mma16816(sacc[2*p+1], qh[k], bl[2], bl[3]);
                mma16816(sacc[2*p],   ql[k], bh[0], bh[1]);
                mma16816(sacc[2*p+1], ql[k], bh[2], bh[3]);
            }
        }

        // ---- epilogue in registers: sigmoid, norm, split into GEMM2 A-frags ----
        uint32_t sh[4][4], sl[4][4];
        #pragma unroll
        for (int kk = 0; kk < 4; kk++) {
            float s0[4], s1[4];
            #pragma unroll
            for (int i = 0; i < 4; i++) {
                s0[i] = sigmoidf_fast(sacc[2*kk][i]);
                s1[i] = sigmoidf_fast(sacc[2*kk+1][i]);
            }
            normLo += (s0[0] + s0[1]) + (s1[0] + s1[1]);
            normHi += (s0[2] + s0[3]) + (s1[2] + s1[3]);
            split2(s0[0], s0[1], sh[kk][0], sl[kk][0]);
            split2(s0[2], s0[3], sh[kk][1], sl[kk][1]);
            split2(s1[0], s1[1], sh[kk][2], sl[kk][2]);
            split2(s1[2], s1[3], sh[kk][3], sl[kk][3]);
        }

        // ---- GEMM2: O[16x64] += S V (sh*vh + sh*vl + sl*vh) ----
        #pragma unroll
        for (int p = 0; p < 4; p++) {          // n (d-col) pair: tiles 2p, 2p+1
            #pragma unroll
            for (int kk = 0; kk < 4; kk++) {   // k (l) step
                const int lrow = kk * 16 + (t4 & 1) * 8 + r8;
                const int dc   = p * 16 + (t4 >> 1) * 8;
                const uint32_t off = sw128(lrow * 128 + dc * 2);
                uint32_t vh[4], vl[4];
                ldmx4t(sb + SVH + off, vh);
                ldmx4t(sb + SVL + off, vl);
                mma16816(oacc[2*p],   sh[kk], vh[0], vh[1]);
                mma16816(oacc[2*p+1], sh[kk], vh[2], vh[3]);
                mma16816(oacc[2*p],   sh[kk], vl[0], vl[1]);
                mma16816(oacc[2*p+1], sh[kk], vl[2], vl[3]);
                mma16816(oacc[2*p],   sl[kk], vh[0], vh[1]);
                mma16816(oacc[2*p+1], sl[kk], vh[2], vh[3]);
            }
        }
        __syncthreads();   // protect K/V tiles before next iteration overwrites
    }

    // ---- finalize: quad-reduce norm (lanes lid&~3 share a row), scale, store ----
    #pragma unroll
    for (int m = 1; m <= 2; m <<= 1) {
        normLo += __shfl_xor_sync(0xffffffffu, normLo, m);
        normHi += __shfl_xor_sync(0xffffffffu, normHi, m);
    }
    const float invLo = 1.0f / normLo;
    const float invHi = 1.0f / normHi;

    const int rowLo = n0 + mw + (lid >> 2);
    const int rowHi = rowLo + 8;
    const int cbase = (lid & 3) * 2;
    #pragma unroll
    for (int j = 0; j < 8; j++) {
        float2 lo = make_float2(oacc[j][0] * invLo, oacc[j][1] * invLo);
        float2 hi = make_float2(oacc[j][2] * invHi, oacc[j][3] * invHi);
        *(float2*)(out + ((size_t)rowLo * HH + h) * DD + j * 8 + cbase) = lo;
        *(float2*)(out + ((size_t)rowHi * HH + h) * DD + j * 8 + cbase) = hi;
    }
}

extern "C" void kernel_launch(void* const* d_in, const int* in_sizes, int n_in,
                              void* d_out, int out_size)
{
    const float* queries = (const float*)d_in[0];
    const float* keys    = (const float*)d_in[1];
    const float* values  = (const float*)d_in[2];
    float* out = (float*)d_out;

    cudaFuncSetAttribute(diffattn_hmma,
                         cudaFuncAttributeMaxDynamicSharedMemorySize, SMEM_BYTES);

    const dim3 grid((NN / BM) * HH);   // 32 * 8 = 256 CTAs
    diffattn_hmma<<<grid, NTHREADS, SMEM_BYTES>>>(queries, keys, values, out);
}